// round 16
// baseline (speedup 1.0000x reference)
#include <cuda_runtime.h>
#include <cuda_bf16.h>
#include <cuda_fp16.h>
#include <cstdint>
#include <math.h>

#define B_DIM 2
#define T_SEQ 2048
#define C_DIM 1024
#define H_DIM 16
#define D_HEAD 64
#define M_ROWS (B_DIM * T_SEQ)       // 4096
#define QKV_COLS (3 * C_DIM)         // 3072

// ---------------------------------------------------------------------------
// Scratch (allocation-free rule: __device__ globals)
// ---------------------------------------------------------------------------
__device__ __half g_qkv16[(size_t)M_ROWS * QKV_COLS]; // qkv fp16 (B,T,3,H,D)

__device__ __half g_x16[(size_t)M_ROWS * C_DIM];     // x fp16
__device__ __half g_wa [(size_t)QKV_COLS * C_DIM];   // w_attn fp16
__device__ __half g_wp [(size_t)C_DIM * C_DIM];      // w_proj fp16
__device__ __half g_yh [(size_t)M_ROWS * C_DIM];     // attention out fp16

// head-major fp16 Q, K: (B,H,T,D)   (V read directly from qkv16 in flash)
#define HD_ELEMS ((size_t)B_DIM * H_DIM * T_SEQ * D_HEAD)
__device__ __half g_Qh [HD_ELEMS];
__device__ __half g_Kh [HD_ELEMS];

// RoPE tables: (t, i) for t in [0,2048), i in [0,32)
__device__ float g_cosT[T_SEQ * 32];
__device__ float g_sinT[T_SEQ * 32];

// ---------------------------------------------------------------------------
// helpers
// ---------------------------------------------------------------------------
__device__ __forceinline__ uint32_t smem_to_u32(const void* smem_ptr) {
    uint32_t addr;
    asm("{ .reg .u64 tmp; cvta.to.shared.u64 tmp, %1; cvt.u32.u64 %0, tmp; }"
        : "=r"(addr) : "l"(smem_ptr));
    return addr;
}

#define CP_ASYNC16(dst_u32, src_ptr) \
    asm volatile("cp.async.cg.shared.global [%0], [%1], 16;" \
        :: "r"(dst_u32), "l"(__cvta_generic_to_global(src_ptr)))
#define CP_COMMIT() asm volatile("cp.async.commit_group;")
#define CP_WAIT1()  asm volatile("cp.async.wait_group 1;")
#define CP_WAIT2()  asm volatile("cp.async.wait_group 2;")
#define CP_WAIT0()  asm volatile("cp.async.wait_group 0;")

__device__ __forceinline__ void ldsm_x4(uint32_t* r, uint32_t addr) {
    asm volatile("ldmatrix.sync.aligned.m8n8.x4.shared.b16 {%0,%1,%2,%3}, [%4];"
        : "=r"(r[0]), "=r"(r[1]), "=r"(r[2]), "=r"(r[3]) : "r"(addr));
}
__device__ __forceinline__ void ldsm_x4t(uint32_t* r, uint32_t addr) {
    asm volatile("ldmatrix.sync.aligned.m8n8.x4.trans.shared.b16 {%0,%1,%2,%3}, [%4];"
        : "=r"(r[0]), "=r"(r[1]), "=r"(r[2]), "=r"(r[3]) : "r"(addr));
}
__device__ __forceinline__ void mma_f16(float* d, const uint32_t* a, const uint32_t* b) {
    asm volatile(
        "mma.sync.aligned.m16n8k16.row.col.f32.f16.f16.f32 "
        "{%0,%1,%2,%3}, {%4,%5,%6,%7}, {%8,%9}, {%0,%1,%2,%3};"
        : "+f"(d[0]), "+f"(d[1]), "+f"(d[2]), "+f"(d[3])
        : "r"(a[0]), "r"(a[1]), "r"(a[2]), "r"(a[3]), "r"(b[0]), "r"(b[1]));
}
__device__ __forceinline__ float ex2f(float x) {
    float r;
    asm("ex2.approx.f32 %0, %1;" : "=f"(r) : "f"(x));
    return r;
}

#define QSCALE (0.125f * 1.4426950408889634f)   // 1/sqrt(64) * log2(e)

// ---------------------------------------------------------------------------
// fused fp32 -> fp16 convert for x, w_attn, w_proj + RoPE table (1 launch)
// ---------------------------------------------------------------------------
#define N4_X  (M_ROWS * C_DIM / 4)
#define N4_WA (QKV_COLS * C_DIM / 4)
#define N4_WP (C_DIM * C_DIM / 4)
#define N4_ALL (N4_X + N4_WA + N4_WP)
#define N_TAB (T_SEQ * 32)
#define N_PREP (N4_ALL + N_TAB)

__global__ void conv_all_kernel(const float* __restrict__ x,
                                const float* __restrict__ waf,
                                const float* __restrict__ wpf,
                                __half* __restrict__ x16,
                                __half* __restrict__ wa,
                                __half* __restrict__ wp,
                                float* __restrict__ cosT,
                                float* __restrict__ sinT)
{
    int i = blockIdx.x * blockDim.x + threadIdx.x;
    if (i >= N4_ALL) {
        int j = i - N4_ALL;
        if (j >= N_TAB) return;
        int t = j >> 5, ii = j & 31;
        float p = powf(10000.0f, (float)(2 * ii) * (1.0f / 64.0f));
        float ang = (float)t * (1.0f / p);
        float sn, cs;
        sincosf(ang, &sn, &cs);
        cosT[j] = cs;
        sinT[j] = sn;
        return;
    }
    const float* src;
    __half* dst;
    int j;
    if (i < N4_X)               { src = x;   dst = x16; j = i; }
    else if (i < N4_X + N4_WA)  { src = waf; dst = wa;  j = i - N4_X; }
    else                        { src = wpf; dst = wp;  j = i - N4_X - N4_WA; }
    float4 v = ((const float4*)src)[j];
    __half2 hp0 = __floats2half2_rn(v.x, v.y);
    __half2 hp1 = __floats2half2_rn(v.z, v.w);
    ((__half2*)dst)[2 * j]     = hp0;
    ((__half2*)dst)[2 * j + 1] = hp1;
}

// ---------------------------------------------------------------------------
// Tensor-core GEMM NT via mma.sync fp16, single pass:
//   C[M,N] = A[M,K] * B[N,K]^T
// 128x128 CTA tile, BK=32, 256 threads (8 warps 2x4, 64x32 warp tiles),
// cp.async 3-stage pipeline, 80B smem pitch. Templated fp16/fp32 output.
// __launch_bounds__(256,3): 3 CTAs/SM (85 regs) to kill wave quantization.
// ---------------------------------------------------------------------------
#define GTILE 10240u                  // 128 rows * 80B
#define GSTAGE (2 * GTILE)            // A, B = 20480
#define GEMM_SMEM (3 * GSTAGE)        // 61440

__device__ __forceinline__ void gemm_load_stage(
    uint32_t sdst,
    const __half* __restrict__ A, const __half* __restrict__ B,
    int bm, int bn, int K, int k0, int tid)
{
#pragma unroll
    for (int i = 0; i < 2; ++i) {
        int idx = tid + i * 256;           // 0..511 -> (row, 16B-chunk)
        int r = idx >> 2, c = idx & 3;
        uint32_t so = (uint32_t)(r * 80 + c * 16);
        CP_ASYNC16(sdst + so,         A + (size_t)(bm + r) * K + k0 + c * 8);
        CP_ASYNC16(sdst + GTILE + so, B + (size_t)(bn + r) * K + k0 + c * 8);
    }
}

template<bool HALF_OUT>
__global__ void __launch_bounds__(256, 3) gemm_f16_kernel(
    const __half* __restrict__ A, const __half* __restrict__ B,
    void* __restrict__ Cv, int N, int K)
{
    extern __shared__ char smem[];
    const uint32_t sb = smem_to_u32(smem);
    const int tid = threadIdx.x;
    const int lane = tid & 31, wid = tid >> 5;
    const int wr = wid >> 2, wc = wid & 3;          // warp grid 2x4
    const int bm = blockIdx.y * 128, bn = blockIdx.x * 128;

    float acc[4][4][4];
#pragma unroll
    for (int mi = 0; mi < 4; ++mi)
#pragma unroll
        for (int ni = 0; ni < 4; ++ni)
#pragma unroll
            for (int j = 0; j < 4; ++j) acc[mi][ni][j] = 0.f;

    const int nk = K >> 5;
    gemm_load_stage(sb, A, B, bm, bn, K, 0, tid);
    CP_COMMIT();
    gemm_load_stage(sb + GSTAGE, A, B, bm, bn, K, 32, tid);
    CP_COMMIT();

    uint32_t bufs[3] = {sb, sb + GSTAGE, sb + 2 * GSTAGE};
    int cur = 0, nxt = 2;

    for (int ks = 0; ks < nk; ++ks) {
        CP_WAIT1();
        __syncthreads();

        if (ks + 2 < nk)
            gemm_load_stage(bufs[nxt], A, B, bm, bn, K, (ks + 2) * 32, tid);
        CP_COMMIT();

        const uint32_t sA = bufs[cur];
        const uint32_t sB = sA + GTILE;

#pragma unroll
        for (int kk = 0; kk < 2; ++kk) {
            const uint32_t colo = (uint32_t)(kk * 32 + (lane >> 4) * 16);
            uint32_t af[4][4], bf[4][2];
#pragma unroll
            for (int mi = 0; mi < 4; ++mi) {
                uint32_t ro = (uint32_t)(wr * 64 + mi * 16 + (lane & 15)) * 80 + colo;
                ldsm_x4(af[mi], sA + ro);
            }
#pragma unroll
            for (int nj = 0; nj < 2; ++nj) {
                uint32_t ro = (uint32_t)(wc * 32 + nj * 16 + (lane & 15)) * 80 + colo;
                uint32_t t[4];
                ldsm_x4(t, sB + ro);
                bf[nj * 2][0] = t[0]; bf[nj * 2][1] = t[2];
                bf[nj * 2 + 1][0] = t[1]; bf[nj * 2 + 1][1] = t[3];
            }
#pragma unroll
            for (int mi = 0; mi < 4; ++mi)
#pragma unroll
                for (int ni = 0; ni < 4; ++ni)
                    mma_f16(acc[mi][ni], af[mi], bf[ni]);
        }

        cur = (cur + 1) % 3;
        nxt = (nxt + 1) % 3;
    }

    // epilogue
#pragma unroll
    for (int mi = 0; mi < 4; ++mi) {
        int row = bm + wr * 64 + mi * 16 + (lane >> 2);
#pragma unroll
        for (int ni = 0; ni < 4; ++ni) {
            int col = bn + wc * 32 + ni * 8 + (lane & 3) * 2;
            if (HALF_OUT) {
                __half* C = (__half*)Cv;
                __half2 h0 = __floats2half2_rn(acc[mi][ni][0], acc[mi][ni][1]);
                __half2 h1 = __floats2half2_rn(acc[mi][ni][2], acc[mi][ni][3]);
                *(__half2*)&C[(size_t)row * N + col] = h0;
                *(__half2*)&C[(size_t)(row + 8) * N + col] = h1;
            } else {
                float* C = (float*)Cv;
                float2 v0 = make_float2(acc[mi][ni][0], acc[mi][ni][1]);
                float2 v1 = make_float2(acc[mi][ni][2], acc[mi][ni][3]);
                *(float2*)&C[(size_t)row * N + col] = v0;
                *(float2*)&C[(size_t)(row + 8) * N + col] = v1;
            }
        }
    }
}

// ---------------------------------------------------------------------------
// Prep: RoPE (q,k only) + head-major relayout. Reads fp16 qkv + tables.
// V stays in qkv16 (flash reads it directly, strided).
// ---------------------------------------------------------------------------
__global__ void rope_split_kernel(const __half* __restrict__ qkv,
                                  const float* __restrict__ cosT,
                                  const float* __restrict__ sinT,
                                  __half* __restrict__ Qh,
                                  __half* __restrict__ Kh)
{
    int idx = blockIdx.x * blockDim.x + threadIdx.x;
    int i = idx & 31;
    int h = (idx >> 5) & 15;
    int t = (idx >> 9) & 2047;
    int b = idx >> 20;

    float cs = cosT[t * 32 + i];
    float sn = sinT[t * 32 + i];

    size_t src = ((size_t)(b * T_SEQ + t)) * QKV_COLS + h * D_HEAD;
    size_t dst = ((size_t)((b * H_DIM + h) * T_SEQ + t)) * D_HEAD;

    // q (fold QSCALE)
    {
        float q1 = __half2float(qkv[src + i]);
        float q2 = __half2float(qkv[src + i + 32]);
        Qh[dst + i]      = __float2half_rn((q1 * cs + q2 * sn) * QSCALE);
        Qh[dst + i + 32] = __float2half_rn((-q1 * sn + q2 * cs) * QSCALE);
    }
    // k
    {
        float k1 = __half2float(qkv[src + C_DIM + i]);
        float k2 = __half2float(qkv[src + C_DIM + i + 32]);
        Kh[dst + i]      = __float2half_rn(k1 * cs + k2 * sn);
        Kh[dst + i + 32] = __float2half_rn(-k1 * sn + k2 * cs);
    }
}

// ---------------------------------------------------------------------------
// Flash attention via mma.sync fp16, causal, exp2 domain.
// CTA: 128 queries x one (b,h); 8 warps x 16 rows. 64-key tiles,
// 3-stage cp.async pipeline; K from head-major Kh, V directly from qkv16
// (128B rows at QKV_COLS stride). Scalar row-sums (shfl).
// ---------------------------------------------------------------------------
#define FPITCH 144u
#define FTILE  (64u * FPITCH)          // 9216
#define FSTAGE (2u * FTILE)            // K, V = 18432
#define FL_SMEM (3u * FSTAGE)          // 55296

__device__ __forceinline__ void flash_load_stage(
    uint32_t dstbase, int kb,
    const __half* __restrict__ Kh, const __half* __restrict__ Vsrc, int tid)
{
#pragma unroll
    for (int j = 0; j < 4; ++j) {
        int idx = tid + j * 256;
        int tile = idx >> 9;
        int r = (idx >> 3) & 63;
        int c = idx & 7;
        uint32_t dst = dstbase + (uint32_t)tile * FTILE + (uint32_t)r * FPITCH + c * 16;
        if (tile == 0)
            CP_ASYNC16(dst, Kh + (size_t)(kb + r) * D_HEAD + c * 8);
        else
            CP_ASYNC16(dst, Vsrc + (size_t)(kb + r) * QKV_COLS + c * 8);
    }
}

__global__ void __launch_bounds__(256, 2) flash_mma_kernel(
    const __half* __restrict__ Qhg,
    const __half* __restrict__ Khg, const __half* __restrict__ qkv16,
    __half* __restrict__ yh)
{
    extern __shared__ char fsm[];
    const uint32_t sb = smem_to_u32(fsm);
    const int tid = threadIdx.x;
    const int lane = tid & 31, w = tid >> 5;
    const int qt = gridDim.x - 1 - blockIdx.x;     // heavy tiles first
    const int bh = blockIdx.y;
    const int b = bh >> 4, h = bh & 15;
    const int qb = qt * 128;

    const size_t hoff = (size_t)bh * T_SEQ * D_HEAD;
    const __half* Qh = Qhg + hoff + (size_t)qb * D_HEAD;
    const __half* Kh = Khg + hoff;
    const __half* Vsrc = qkv16 + (size_t)(b * T_SEQ) * QKV_COLS + 2 * C_DIM + h * D_HEAD;

    uint32_t bufs[3] = {sb, sb + FSTAGE, sb + 2 * FSTAGE};

    // ---- issue Q load (buf0 region), then prefetch K/V stages into bufs 1/2 ----
#pragma unroll
    for (int j = 0; j < 4; ++j) {
        int idx = tid + j * 256;
        int r = idx >> 3;
        int c = idx & 7;
        CP_ASYNC16(sb + (uint32_t)r * FPITCH + c * 16,
                   Qh + (size_t)r * D_HEAD + c * 8);
    }
    CP_COMMIT();                                   // group: Q
    flash_load_stage(bufs[1], 0, Kh, Vsrc, tid);
    CP_COMMIT();                                   // group: stage0
    flash_load_stage(bufs[2], 64, Kh, Vsrc, tid);
    CP_COMMIT();                                   // group: stage1

    CP_WAIT2();                                    // Q complete
    __syncthreads();

    uint32_t qhf[4][4];
    {
        uint32_t arow = (uint32_t)(w * 16 + (lane & 7) + ((lane & 8) ? 8 : 0));
        uint32_t acol = (uint32_t)(((lane & 16) ? 16 : 0));
#pragma unroll
        for (int kk = 0; kk < 4; ++kk)
            ldsm_x4(qhf[kk], sb + arow * FPITCH + kk * 32 + acol);
    }
    __syncthreads();   // Q fragments extracted; buf0 reusable

    float o[8][4];
#pragma unroll
    for (int j = 0; j < 8; ++j)
#pragma unroll
        for (int c = 0; c < 4; ++c) o[j][c] = 0.f;
    float m0 = -1e30f, m1 = -1e30f, l0 = 0.f, l1 = 0.f;

    const int ntiles = 2 * qt + 2;
    const int wqmin = qb + w * 16;
    const int wqmax = wqmin + 15;

    int cur = 1, nxt = 0;   // stages 0/1 live in bufs 1/2; next load -> buf 0

    for (int kt = 0; kt < ntiles; ++kt) {
        CP_WAIT1();
        __syncthreads();

        if (kt + 2 < ntiles)
            flash_load_stage(bufs[nxt], (kt + 2) * 64, Kh, Vsrc, tid);
        CP_COMMIT();

        const uint32_t stage = bufs[cur];
        const int kb = kt * 64;

        if (kb <= wqmax) {
            // ---- S = Q K^T ----
            float s[8][4];
#pragma unroll
            for (int j = 0; j < 8; ++j)
#pragma unroll
                for (int c = 0; c < 4; ++c) s[j][c] = 0.f;

            const uint32_t br = (uint32_t)((lane & 7) + ((lane & 16) ? 8 : 0));
            const uint32_t bc = (uint32_t)((lane & 8) ? 16 : 0);
#pragma unroll
            for (int kg = 0; kg < 4; ++kg) {
                uint32_t rowa = (uint32_t)(kg * 16) + br;
#pragma unroll
                for (int kk = 0; kk < 4; ++kk) {
                    uint32_t addr = stage + rowa * FPITCH + kk * 32 + bc;
                    uint32_t k4[4];
                    ldsm_x4(k4, addr);
                    mma_f16(s[2 * kg],     qhf[kk], &k4[0]);
                    mma_f16(s[2 * kg + 1], qhf[kk], &k4[2]);
                }
            }

            // ---- causal mask ----
            if (kb + 63 > wqmin) {
                int r0 = wqmin + (lane >> 2), r1 = r0 + 8;
#pragma unroll
                for (int j = 0; j < 8; ++j) {
                    int k0 = kb + j * 8 + ((lane & 3) << 1);
                    if (k0 > r0)     s[j][0] = -1e30f;
                    if (k0 + 1 > r0) s[j][1] = -1e30f;
                    if (k0 > r1)     s[j][2] = -1e30f;
                    if (k0 + 1 > r1) s[j][3] = -1e30f;
                }
            }

            // ---- online softmax (exp2 domain, scalar sums) ----
            float mx0 = -1e30f, mx1 = -1e30f;
#pragma unroll
            for (int j = 0; j < 8; ++j) {
                mx0 = fmaxf(mx0, fmaxf(s[j][0], s[j][1]));
                mx1 = fmaxf(mx1, fmaxf(s[j][2], s[j][3]));
            }
            mx0 = fmaxf(mx0, __shfl_xor_sync(0xffffffffu, mx0, 1));
            mx0 = fmaxf(mx0, __shfl_xor_sync(0xffffffffu, mx0, 2));
            mx1 = fmaxf(mx1, __shfl_xor_sync(0xffffffffu, mx1, 1));
            mx1 = fmaxf(mx1, __shfl_xor_sync(0xffffffffu, mx1, 2));
            float m0n = fmaxf(m0, mx0), m1n = fmaxf(m1, mx1);
            float sc0 = ex2f(m0 - m0n), sc1 = ex2f(m1 - m1n);
            float rs0 = 0.f, rs1 = 0.f;
#pragma unroll
            for (int j = 0; j < 8; ++j) {
                s[j][0] = ex2f(s[j][0] - m0n);
                s[j][1] = ex2f(s[j][1] - m0n);
                s[j][2] = ex2f(s[j][2] - m1n);
                s[j][3] = ex2f(s[j][3] - m1n);
                rs0 += s[j][0] + s[j][1];
                rs1 += s[j][2] + s[j][3];
            }
            rs0 += __shfl_xor_sync(0xffffffffu, rs0, 1);
            rs0 += __shfl_xor_sync(0xffffffffu, rs0, 2);
            rs1 += __shfl_xor_sync(0xffffffffu, rs1, 1);
            rs1 += __shfl_xor_sync(0xffffffffu, rs1, 2);
            l0 = l0 * sc0 + rs0;
            l1 = l1 * sc1 + rs1;
            m0 = m0n; m1 = m1n;
#pragma unroll
            for (int j = 0; j < 8; ++j) {
                o[j][0] *= sc0; o[j][1] *= sc0;
                o[j][2] *= sc1; o[j][3] *= sc1;
            }

            // ---- pack P fp16 A-fragments ----
            uint32_t aph[4][4];
#pragma unroll
            for (int kk2 = 0; kk2 < 4; ++kk2) {
                int j0 = 2 * kk2, j1 = j0 + 1;
                __half2 p0 = __floats2half2_rn(s[j0][0], s[j0][1]);
                __half2 p1 = __floats2half2_rn(s[j0][2], s[j0][3]);
                __half2 p2 = __floats2half2_rn(s[j1][0], s[j1][1]);
                __half2 p3 = __floats2half2_rn(s[j1][2], s[j1][3]);
                aph[kk2][0] = *(uint32_t*)&p0;
                aph[kk2][1] = *(uint32_t*)&p1;
                aph[kk2][2] = *(uint32_t*)&p2;
                aph[kk2][3] = *(uint32_t*)&p3;
            }

            // ---- O += P V via ldmatrix.trans on V ----
            const uint32_t vr = (uint32_t)((lane & 7) + ((lane & 8) ? 8 : 0));
            const uint32_t vc = (uint32_t)((lane & 16) ? 16 : 0);
#pragma unroll
            for (int dg = 0; dg < 4; ++dg) {
#pragma unroll
                for (int kk2 = 0; kk2 < 4; ++kk2) {
                    uint32_t addr = stage + FTILE +
                                    (uint32_t)(kk2 * 16 + vr) * FPITCH + dg * 32 + vc;
                    uint32_t v4[4];
                    ldsm_x4t(v4, addr);
                    mma_f16(o[2 * dg],     aph[kk2], &v4[0]);
                    mma_f16(o[2 * dg + 1], aph[kk2], &v4[2]);
                }
            }
        }

        cur = (cur + 1) % 3;
        nxt = (nxt + 1) % 3;
    }

    // ---- normalize and write fp16 (proj GEMM A-operand) ----
    const float inv0 = 1.0f / l0, inv1 = 1.0f / l1;
    const int r0 = qb + w * 16 + (lane >> 2);
#pragma unroll
    for (int j = 0; j < 8; ++j) {
        int col = h * 64 + j * 8 + (lane & 3) * 2;
        __half2 hh0 = __floats2half2_rn(o[j][0] * inv0, o[j][1] * inv0);
        __half2 hh1 = __floats2half2_rn(o[j][2] * inv1, o[j][3] * inv1);
        *(__half2*)&yh[(size_t)(b * T_SEQ + r0) * C_DIM + col] = hh0;
        *(__half2*)&yh[(size_t)(b * T_SEQ + r0 + 8) * C_DIM + col] = hh1;
    }
}

// ---------------------------------------------------------------------------
extern "C" void kernel_launch(void* const* d_in, const int* in_sizes, int n_in,
                              void* d_out, int out_size)
{
    const float* x      = (const float*)d_in[0];
    const float* w_attn = (const float*)d_in[1];
    const float* w_proj = (const float*)d_in[2];
    float* out = (float*)d_out;

    __half *qkv16, *x16, *wa, *wp, *yh;
    __half *Qh, *Kh;
    float *cosT, *sinT;
    cudaGetSymbolAddress((void**)&qkv16, g_qkv16);
    cudaGetSymbolAddress((void**)&x16, g_x16);
    cudaGetSymbolAddress((void**)&wa, g_wa);
    cudaGetSymbolAddress((void**)&wp, g_wp);
    cudaGetSymbolAddress((void**)&yh, g_yh);
    cudaGetSymbolAddress((void**)&Qh, g_Qh);
    cudaGetSymbolAddress((void**)&Kh, g_Kh);
    cudaGetSymbolAddress((void**)&cosT, g_cosT);
    cudaGetSymbolAddress((void**)&sinT, g_sinT);

    static bool attr_set = false;
    if (!attr_set) {
        cudaFuncSetAttribute(gemm_f16_kernel<true>,
                             cudaFuncAttributeMaxDynamicSharedMemorySize, GEMM_SMEM);
        cudaFuncSetAttribute(gemm_f16_kernel<false>,
                             cudaFuncAttributeMaxDynamicSharedMemorySize, GEMM_SMEM);
        cudaFuncSetAttribute(flash_mma_kernel,
                             cudaFuncAttributeMaxDynamicSharedMemorySize, FL_SMEM);
        attr_set = true;
    }

    // fused input conversions + RoPE tables (1 launch)
    conv_all_kernel<<<(N_PREP + 255) / 256, 256>>>(x, w_attn, w_proj,
                                                   x16, wa, wp, cosT, sinT);

    // 1) qkv = x @ w_attn^T   (fp16 HMMA, fp16 output; 3 CTAs/SM)
    {
        dim3 grid(QKV_COLS / 128, M_ROWS / 128);
        gemm_f16_kernel<true><<<grid, 256, GEMM_SMEM>>>(x16, wa, qkv16,
                                                        QKV_COLS, C_DIM);
    }
    // 2) RoPE (table-based) q,k only -> head-major
    {
        int total = B_DIM * T_SEQ * H_DIM * 32;
        rope_split_kernel<<<total / 256, 256>>>(qkv16, cosT, sinT, Qh, Kh);
    }
    // 3) flash attention (V read from qkv16) -> yh fp16
    {
        dim3 grid(T_SEQ / 128, B_DIM * H_DIM);
        flash_mma_kernel<<<grid, 256, FL_SMEM>>>(Qh, Kh, qkv16, yh);
    }
    // 4) out = y @ w_proj^T   (fp16 HMMA, fp32 output; 3 CTAs/SM)
    {
        dim3 grid(C_DIM / 128, M_ROWS / 128);
        gemm_f16_kernel<false><<<grid, 256, GEMM_SMEM>>>(yh, wp, out,
                                                         C_DIM, C_DIM);
    }
}

// round 17
// speedup vs baseline: 1.2782x; 1.2782x over previous
#include <cuda_runtime.h>
#include <cuda_bf16.h>
#include <cuda_fp16.h>
#include <cstdint>
#include <math.h>

#define B_DIM 2
#define T_SEQ 2048
#define C_DIM 1024
#define H_DIM 16
#define D_HEAD 64
#define M_ROWS (B_DIM * T_SEQ)       // 4096
#define QKV_COLS (3 * C_DIM)         // 3072

// ---------------------------------------------------------------------------
// Scratch (allocation-free rule: __device__ globals)
// ---------------------------------------------------------------------------
__device__ __half g_qkv16[(size_t)M_ROWS * QKV_COLS]; // qkv fp16 (B,T,3,H,D)

__device__ __half g_x16[(size_t)M_ROWS * C_DIM];     // x fp16
__device__ __half g_wa [(size_t)QKV_COLS * C_DIM];   // w_attn fp16
__device__ __half g_wp [(size_t)C_DIM * C_DIM];      // w_proj fp16
__device__ __half g_yh [(size_t)M_ROWS * C_DIM];     // attention out fp16

// head-major fp16 Q, K: (B,H,T,D)   (V read directly from qkv16 in flash)
#define HD_ELEMS ((size_t)B_DIM * H_DIM * T_SEQ * D_HEAD)
__device__ __half g_Qh [HD_ELEMS];
__device__ __half g_Kh [HD_ELEMS];

// RoPE tables: (t, i) for t in [0,2048), i in [0,32)
__device__ float g_cosT[T_SEQ * 32];
__device__ float g_sinT[T_SEQ * 32];

// ---------------------------------------------------------------------------
// helpers
// ---------------------------------------------------------------------------
__device__ __forceinline__ uint32_t smem_to_u32(const void* smem_ptr) {
    uint32_t addr;
    asm("{ .reg .u64 tmp; cvta.to.shared.u64 tmp, %1; cvt.u32.u64 %0, tmp; }"
        : "=r"(addr) : "l"(smem_ptr));
    return addr;
}

#define CP_ASYNC16(dst_u32, src_ptr) \
    asm volatile("cp.async.cg.shared.global [%0], [%1], 16;" \
        :: "r"(dst_u32), "l"(__cvta_generic_to_global(src_ptr)))
#define CP_COMMIT() asm volatile("cp.async.commit_group;")
#define CP_WAIT1()  asm volatile("cp.async.wait_group 1;")
#define CP_WAIT2()  asm volatile("cp.async.wait_group 2;")
#define CP_WAIT0()  asm volatile("cp.async.wait_group 0;")

__device__ __forceinline__ void ldsm_x4(uint32_t* r, uint32_t addr) {
    asm volatile("ldmatrix.sync.aligned.m8n8.x4.shared.b16 {%0,%1,%2,%3}, [%4];"
        : "=r"(r[0]), "=r"(r[1]), "=r"(r[2]), "=r"(r[3]) : "r"(addr));
}
__device__ __forceinline__ void ldsm_x4t(uint32_t* r, uint32_t addr) {
    asm volatile("ldmatrix.sync.aligned.m8n8.x4.trans.shared.b16 {%0,%1,%2,%3}, [%4];"
        : "=r"(r[0]), "=r"(r[1]), "=r"(r[2]), "=r"(r[3]) : "r"(addr));
}
__device__ __forceinline__ void mma_f16(float* d, const uint32_t* a, const uint32_t* b) {
    asm volatile(
        "mma.sync.aligned.m16n8k16.row.col.f32.f16.f16.f32 "
        "{%0,%1,%2,%3}, {%4,%5,%6,%7}, {%8,%9}, {%0,%1,%2,%3};"
        : "+f"(d[0]), "+f"(d[1]), "+f"(d[2]), "+f"(d[3])
        : "r"(a[0]), "r"(a[1]), "r"(a[2]), "r"(a[3]), "r"(b[0]), "r"(b[1]));
}
__device__ __forceinline__ float ex2f(float x) {
    float r;
    asm("ex2.approx.f32 %0, %1;" : "=f"(r) : "f"(x));
    return r;
}

#define QSCALE (0.125f * 1.4426950408889634f)   // 1/sqrt(64) * log2(e)

// ---------------------------------------------------------------------------
// fused fp32 -> fp16 convert for x, w_attn, w_proj + RoPE table (1 launch)
// ---------------------------------------------------------------------------
#define N4_X  (M_ROWS * C_DIM / 4)
#define N4_WA (QKV_COLS * C_DIM / 4)
#define N4_WP (C_DIM * C_DIM / 4)
#define N4_ALL (N4_X + N4_WA + N4_WP)
#define N_TAB (T_SEQ * 32)
#define N_PREP (N4_ALL + N_TAB)

__global__ void conv_all_kernel(const float* __restrict__ x,
                                const float* __restrict__ waf,
                                const float* __restrict__ wpf,
                                __half* __restrict__ x16,
                                __half* __restrict__ wa,
                                __half* __restrict__ wp,
                                float* __restrict__ cosT,
                                float* __restrict__ sinT)
{
    int i = blockIdx.x * blockDim.x + threadIdx.x;
    if (i >= N4_ALL) {
        int j = i - N4_ALL;
        if (j >= N_TAB) return;
        int t = j >> 5, ii = j & 31;
        float p = powf(10000.0f, (float)(2 * ii) * (1.0f / 64.0f));
        float ang = (float)t * (1.0f / p);
        float sn, cs;
        sincosf(ang, &sn, &cs);
        cosT[j] = cs;
        sinT[j] = sn;
        return;
    }
    const float* src;
    __half* dst;
    int j;
    if (i < N4_X)               { src = x;   dst = x16; j = i; }
    else if (i < N4_X + N4_WA)  { src = waf; dst = wa;  j = i - N4_X; }
    else                        { src = wpf; dst = wp;  j = i - N4_X - N4_WA; }
    float4 v = ((const float4*)src)[j];
    __half2 hp0 = __floats2half2_rn(v.x, v.y);
    __half2 hp1 = __floats2half2_rn(v.z, v.w);
    ((__half2*)dst)[2 * j]     = hp0;
    ((__half2*)dst)[2 * j + 1] = hp1;
}

// ---------------------------------------------------------------------------
// Tensor-core GEMM NT via mma.sync fp16, single pass:
//   C[M,N] = A[M,K] * B[N,K]^T
// 128x128 CTA tile, BK=32, 256 threads (8 warps 2x4, 64x32 warp tiles),
// cp.async 3-stage pipeline, 80B smem pitch. Templated fp16/fp32 output.
// Plain launch bounds: 92 regs, 2 CTAs/SM (3-CTA attempt spilled; reverted).
// ---------------------------------------------------------------------------
#define GTILE 10240u                  // 128 rows * 80B
#define GSTAGE (2 * GTILE)            // A, B = 20480
#define GEMM_SMEM (3 * GSTAGE)        // 61440

__device__ __forceinline__ void gemm_load_stage(
    uint32_t sdst,
    const __half* __restrict__ A, const __half* __restrict__ B,
    int bm, int bn, int K, int k0, int tid)
{
#pragma unroll
    for (int i = 0; i < 2; ++i) {
        int idx = tid + i * 256;           // 0..511 -> (row, 16B-chunk)
        int r = idx >> 2, c = idx & 3;
        uint32_t so = (uint32_t)(r * 80 + c * 16);
        CP_ASYNC16(sdst + so,         A + (size_t)(bm + r) * K + k0 + c * 8);
        CP_ASYNC16(sdst + GTILE + so, B + (size_t)(bn + r) * K + k0 + c * 8);
    }
}

template<bool HALF_OUT>
__global__ void __launch_bounds__(256) gemm_f16_kernel(
    const __half* __restrict__ A, const __half* __restrict__ B,
    void* __restrict__ Cv, int N, int K)
{
    extern __shared__ char smem[];
    const uint32_t sb = smem_to_u32(smem);
    const int tid = threadIdx.x;
    const int lane = tid & 31, wid = tid >> 5;
    const int wr = wid >> 2, wc = wid & 3;          // warp grid 2x4
    const int bm = blockIdx.y * 128, bn = blockIdx.x * 128;

    float acc[4][4][4];
#pragma unroll
    for (int mi = 0; mi < 4; ++mi)
#pragma unroll
        for (int ni = 0; ni < 4; ++ni)
#pragma unroll
            for (int j = 0; j < 4; ++j) acc[mi][ni][j] = 0.f;

    const int nk = K >> 5;
    gemm_load_stage(sb, A, B, bm, bn, K, 0, tid);
    CP_COMMIT();
    gemm_load_stage(sb + GSTAGE, A, B, bm, bn, K, 32, tid);
    CP_COMMIT();

    uint32_t bufs[3] = {sb, sb + GSTAGE, sb + 2 * GSTAGE};
    int cur = 0, nxt = 2;

    for (int ks = 0; ks < nk; ++ks) {
        CP_WAIT1();
        __syncthreads();

        if (ks + 2 < nk)
            gemm_load_stage(bufs[nxt], A, B, bm, bn, K, (ks + 2) * 32, tid);
        CP_COMMIT();

        const uint32_t sA = bufs[cur];
        const uint32_t sB = sA + GTILE;

#pragma unroll
        for (int kk = 0; kk < 2; ++kk) {
            const uint32_t colo = (uint32_t)(kk * 32 + (lane >> 4) * 16);
            uint32_t af[4][4], bf[4][2];
#pragma unroll
            for (int mi = 0; mi < 4; ++mi) {
                uint32_t ro = (uint32_t)(wr * 64 + mi * 16 + (lane & 15)) * 80 + colo;
                ldsm_x4(af[mi], sA + ro);
            }
#pragma unroll
            for (int nj = 0; nj < 2; ++nj) {
                uint32_t ro = (uint32_t)(wc * 32 + nj * 16 + (lane & 15)) * 80 + colo;
                uint32_t t[4];
                ldsm_x4(t, sB + ro);
                bf[nj * 2][0] = t[0]; bf[nj * 2][1] = t[2];
                bf[nj * 2 + 1][0] = t[1]; bf[nj * 2 + 1][1] = t[3];
            }
#pragma unroll
            for (int mi = 0; mi < 4; ++mi)
#pragma unroll
                for (int ni = 0; ni < 4; ++ni)
                    mma_f16(acc[mi][ni], af[mi], bf[ni]);
        }

        cur = (cur + 1) % 3;
        nxt = (nxt + 1) % 3;
    }

    // epilogue
#pragma unroll
    for (int mi = 0; mi < 4; ++mi) {
        int row = bm + wr * 64 + mi * 16 + (lane >> 2);
#pragma unroll
        for (int ni = 0; ni < 4; ++ni) {
            int col = bn + wc * 32 + ni * 8 + (lane & 3) * 2;
            if (HALF_OUT) {
                __half* C = (__half*)Cv;
                __half2 h0 = __floats2half2_rn(acc[mi][ni][0], acc[mi][ni][1]);
                __half2 h1 = __floats2half2_rn(acc[mi][ni][2], acc[mi][ni][3]);
                *(__half2*)&C[(size_t)row * N + col] = h0;
                *(__half2*)&C[(size_t)(row + 8) * N + col] = h1;
            } else {
                float* C = (float*)Cv;
                float2 v0 = make_float2(acc[mi][ni][0], acc[mi][ni][1]);
                float2 v1 = make_float2(acc[mi][ni][2], acc[mi][ni][3]);
                *(float2*)&C[(size_t)row * N + col] = v0;
                *(float2*)&C[(size_t)(row + 8) * N + col] = v1;
            }
        }
    }
}

// ---------------------------------------------------------------------------
// Prep: RoPE (q,k only) + head-major relayout. Reads fp16 qkv + tables.
// V stays in qkv16 (flash reads it directly, strided).
// ---------------------------------------------------------------------------
__global__ void rope_split_kernel(const __half* __restrict__ qkv,
                                  const float* __restrict__ cosT,
                                  const float* __restrict__ sinT,
                                  __half* __restrict__ Qh,
                                  __half* __restrict__ Kh)
{
    int idx = blockIdx.x * blockDim.x + threadIdx.x;
    int i = idx & 31;
    int h = (idx >> 5) & 15;
    int t = (idx >> 9) & 2047;
    int b = idx >> 20;

    float cs = cosT[t * 32 + i];
    float sn = sinT[t * 32 + i];

    size_t src = ((size_t)(b * T_SEQ + t)) * QKV_COLS + h * D_HEAD;
    size_t dst = ((size_t)((b * H_DIM + h) * T_SEQ + t)) * D_HEAD;

    // q (fold QSCALE)
    {
        float q1 = __half2float(qkv[src + i]);
        float q2 = __half2float(qkv[src + i + 32]);
        Qh[dst + i]      = __float2half_rn((q1 * cs + q2 * sn) * QSCALE);
        Qh[dst + i + 32] = __float2half_rn((-q1 * sn + q2 * cs) * QSCALE);
    }
    // k
    {
        float k1 = __half2float(qkv[src + C_DIM + i]);
        float k2 = __half2float(qkv[src + C_DIM + i + 32]);
        Kh[dst + i]      = __float2half_rn(k1 * cs + k2 * sn);
        Kh[dst + i + 32] = __float2half_rn(-k1 * sn + k2 * cs);
    }
}

// ---------------------------------------------------------------------------
// Flash attention via mma.sync fp16, causal, exp2 domain.
// CTA: 128 queries x one (b,h); 8 warps x 16 rows. 64-key tiles,
// 3-stage cp.async pipeline; K from head-major Kh, V directly from qkv16
// (128B rows at QKV_COLS stride). Scalar row-sums (shfl).
// ---------------------------------------------------------------------------
#define FPITCH 144u
#define FTILE  (64u * FPITCH)          // 9216
#define FSTAGE (2u * FTILE)            // K, V = 18432
#define FL_SMEM (3u * FSTAGE)          // 55296

__device__ __forceinline__ void flash_load_stage(
    uint32_t dstbase, int kb,
    const __half* __restrict__ Kh, const __half* __restrict__ Vsrc, int tid)
{
#pragma unroll
    for (int j = 0; j < 4; ++j) {
        int idx = tid + j * 256;
        int tile = idx >> 9;
        int r = (idx >> 3) & 63;
        int c = idx & 7;
        uint32_t dst = dstbase + (uint32_t)tile * FTILE + (uint32_t)r * FPITCH + c * 16;
        if (tile == 0)
            CP_ASYNC16(dst, Kh + (size_t)(kb + r) * D_HEAD + c * 8);
        else
            CP_ASYNC16(dst, Vsrc + (size_t)(kb + r) * QKV_COLS + c * 8);
    }
}

__global__ void __launch_bounds__(256, 2) flash_mma_kernel(
    const __half* __restrict__ Qhg,
    const __half* __restrict__ Khg, const __half* __restrict__ qkv16,
    __half* __restrict__ yh)
{
    extern __shared__ char fsm[];
    const uint32_t sb = smem_to_u32(fsm);
    const int tid = threadIdx.x;
    const int lane = tid & 31, w = tid >> 5;
    const int qt = gridDim.x - 1 - blockIdx.x;     // heavy tiles first
    const int bh = blockIdx.y;
    const int b = bh >> 4, h = bh & 15;
    const int qb = qt * 128;

    const size_t hoff = (size_t)bh * T_SEQ * D_HEAD;
    const __half* Qh = Qhg + hoff + (size_t)qb * D_HEAD;
    const __half* Kh = Khg + hoff;
    const __half* Vsrc = qkv16 + (size_t)(b * T_SEQ) * QKV_COLS + 2 * C_DIM + h * D_HEAD;

    uint32_t bufs[3] = {sb, sb + FSTAGE, sb + 2 * FSTAGE};

    // ---- issue Q load (buf0 region), then prefetch K/V stages into bufs 1/2 ----
#pragma unroll
    for (int j = 0; j < 4; ++j) {
        int idx = tid + j * 256;
        int r = idx >> 3;
        int c = idx & 7;
        CP_ASYNC16(sb + (uint32_t)r * FPITCH + c * 16,
                   Qh + (size_t)r * D_HEAD + c * 8);
    }
    CP_COMMIT();                                   // group: Q
    flash_load_stage(bufs[1], 0, Kh, Vsrc, tid);
    CP_COMMIT();                                   // group: stage0
    flash_load_stage(bufs[2], 64, Kh, Vsrc, tid);
    CP_COMMIT();                                   // group: stage1

    CP_WAIT2();                                    // Q complete
    __syncthreads();

    uint32_t qhf[4][4];
    {
        uint32_t arow = (uint32_t)(w * 16 + (lane & 7) + ((lane & 8) ? 8 : 0));
        uint32_t acol = (uint32_t)(((lane & 16) ? 16 : 0));
#pragma unroll
        for (int kk = 0; kk < 4; ++kk)
            ldsm_x4(qhf[kk], sb + arow * FPITCH + kk * 32 + acol);
    }
    __syncthreads();   // Q fragments extracted; buf0 reusable

    float o[8][4];
#pragma unroll
    for (int j = 0; j < 8; ++j)
#pragma unroll
        for (int c = 0; c < 4; ++c) o[j][c] = 0.f;
    float m0 = -1e30f, m1 = -1e30f, l0 = 0.f, l1 = 0.f;

    const int ntiles = 2 * qt + 2;
    const int wqmin = qb + w * 16;
    const int wqmax = wqmin + 15;

    int cur = 1, nxt = 0;   // stages 0/1 live in bufs 1/2; next load -> buf 0

    for (int kt = 0; kt < ntiles; ++kt) {
        CP_WAIT1();
        __syncthreads();

        if (kt + 2 < ntiles)
            flash_load_stage(bufs[nxt], (kt + 2) * 64, Kh, Vsrc, tid);
        CP_COMMIT();

        const uint32_t stage = bufs[cur];
        const int kb = kt * 64;

        if (kb <= wqmax) {
            // ---- S = Q K^T ----
            float s[8][4];
#pragma unroll
            for (int j = 0; j < 8; ++j)
#pragma unroll
                for (int c = 0; c < 4; ++c) s[j][c] = 0.f;

            const uint32_t br = (uint32_t)((lane & 7) + ((lane & 16) ? 8 : 0));
            const uint32_t bc = (uint32_t)((lane & 8) ? 16 : 0);
#pragma unroll
            for (int kg = 0; kg < 4; ++kg) {
                uint32_t rowa = (uint32_t)(kg * 16) + br;
#pragma unroll
                for (int kk = 0; kk < 4; ++kk) {
                    uint32_t addr = stage + rowa * FPITCH + kk * 32 + bc;
                    uint32_t k4[4];
                    ldsm_x4(k4, addr);
                    mma_f16(s[2 * kg],     qhf[kk], &k4[0]);
                    mma_f16(s[2 * kg + 1], qhf[kk], &k4[2]);
                }
            }

            // ---- causal mask ----
            if (kb + 63 > wqmin) {
                int r0 = wqmin + (lane >> 2), r1 = r0 + 8;
#pragma unroll
                for (int j = 0; j < 8; ++j) {
                    int k0 = kb + j * 8 + ((lane & 3) << 1);
                    if (k0 > r0)     s[j][0] = -1e30f;
                    if (k0 + 1 > r0) s[j][1] = -1e30f;
                    if (k0 > r1)     s[j][2] = -1e30f;
                    if (k0 + 1 > r1) s[j][3] = -1e30f;
                }
            }

            // ---- online softmax (exp2 domain, scalar sums) ----
            float mx0 = -1e30f, mx1 = -1e30f;
#pragma unroll
            for (int j = 0; j < 8; ++j) {
                mx0 = fmaxf(mx0, fmaxf(s[j][0], s[j][1]));
                mx1 = fmaxf(mx1, fmaxf(s[j][2], s[j][3]));
            }
            mx0 = fmaxf(mx0, __shfl_xor_sync(0xffffffffu, mx0, 1));
            mx0 = fmaxf(mx0, __shfl_xor_sync(0xffffffffu, mx0, 2));
            mx1 = fmaxf(mx1, __shfl_xor_sync(0xffffffffu, mx1, 1));
            mx1 = fmaxf(mx1, __shfl_xor_sync(0xffffffffu, mx1, 2));
            float m0n = fmaxf(m0, mx0), m1n = fmaxf(m1, mx1);
            float sc0 = ex2f(m0 - m0n), sc1 = ex2f(m1 - m1n);
            float rs0 = 0.f, rs1 = 0.f;
#pragma unroll
            for (int j = 0; j < 8; ++j) {
                s[j][0] = ex2f(s[j][0] - m0n);
                s[j][1] = ex2f(s[j][1] - m0n);
                s[j][2] = ex2f(s[j][2] - m1n);
                s[j][3] = ex2f(s[j][3] - m1n);
                rs0 += s[j][0] + s[j][1];
                rs1 += s[j][2] + s[j][3];
            }
            rs0 += __shfl_xor_sync(0xffffffffu, rs0, 1);
            rs0 += __shfl_xor_sync(0xffffffffu, rs0, 2);
            rs1 += __shfl_xor_sync(0xffffffffu, rs1, 1);
            rs1 += __shfl_xor_sync(0xffffffffu, rs1, 2);
            l0 = l0 * sc0 + rs0;
            l1 = l1 * sc1 + rs1;
            m0 = m0n; m1 = m1n;
#pragma unroll
            for (int j = 0; j < 8; ++j) {
                o[j][0] *= sc0; o[j][1] *= sc0;
                o[j][2] *= sc1; o[j][3] *= sc1;
            }

            // ---- pack P fp16 A-fragments ----
            uint32_t aph[4][4];
#pragma unroll
            for (int kk2 = 0; kk2 < 4; ++kk2) {
                int j0 = 2 * kk2, j1 = j0 + 1;
                __half2 p0 = __floats2half2_rn(s[j0][0], s[j0][1]);
                __half2 p1 = __floats2half2_rn(s[j0][2], s[j0][3]);
                __half2 p2 = __floats2half2_rn(s[j1][0], s[j1][1]);
                __half2 p3 = __floats2half2_rn(s[j1][2], s[j1][3]);
                aph[kk2][0] = *(uint32_t*)&p0;
                aph[kk2][1] = *(uint32_t*)&p1;
                aph[kk2][2] = *(uint32_t*)&p2;
                aph[kk2][3] = *(uint32_t*)&p3;
            }

            // ---- O += P V via ldmatrix.trans on V ----
            const uint32_t vr = (uint32_t)((lane & 7) + ((lane & 8) ? 8 : 0));
            const uint32_t vc = (uint32_t)((lane & 16) ? 16 : 0);
#pragma unroll
            for (int dg = 0; dg < 4; ++dg) {
#pragma unroll
                for (int kk2 = 0; kk2 < 4; ++kk2) {
                    uint32_t addr = stage + FTILE +
                                    (uint32_t)(kk2 * 16 + vr) * FPITCH + dg * 32 + vc;
                    uint32_t v4[4];
                    ldsm_x4t(v4, addr);
                    mma_f16(o[2 * dg],     aph[kk2], &v4[0]);
                    mma_f16(o[2 * dg + 1], aph[kk2], &v4[2]);
                }
            }
        }

        cur = (cur + 1) % 3;
        nxt = (nxt + 1) % 3;
    }

    // ---- normalize and write fp16 (proj GEMM A-operand) ----
    const float inv0 = 1.0f / l0, inv1 = 1.0f / l1;
    const int r0 = qb + w * 16 + (lane >> 2);
#pragma unroll
    for (int j = 0; j < 8; ++j) {
        int col = h * 64 + j * 8 + (lane & 3) * 2;
        __half2 hh0 = __floats2half2_rn(o[j][0] * inv0, o[j][1] * inv0);
        __half2 hh1 = __floats2half2_rn(o[j][2] * inv1, o[j][3] * inv1);
        *(__half2*)&yh[(size_t)(b * T_SEQ + r0) * C_DIM + col] = hh0;
        *(__half2*)&yh[(size_t)(b * T_SEQ + r0 + 8) * C_DIM + col] = hh1;
    }
}

// ---------------------------------------------------------------------------
extern "C" void kernel_launch(void* const* d_in, const int* in_sizes, int n_in,
                              void* d_out, int out_size)
{
    const float* x      = (const float*)d_in[0];
    const float* w_attn = (const float*)d_in[1];
    const float* w_proj = (const float*)d_in[2];
    float* out = (float*)d_out;

    __half *qkv16, *x16, *wa, *wp, *yh;
    __half *Qh, *Kh;
    float *cosT, *sinT;
    cudaGetSymbolAddress((void**)&qkv16, g_qkv16);
    cudaGetSymbolAddress((void**)&x16, g_x16);
    cudaGetSymbolAddress((void**)&wa, g_wa);
    cudaGetSymbolAddress((void**)&wp, g_wp);
    cudaGetSymbolAddress((void**)&yh, g_yh);
    cudaGetSymbolAddress((void**)&Qh, g_Qh);
    cudaGetSymbolAddress((void**)&Kh, g_Kh);
    cudaGetSymbolAddress((void**)&cosT, g_cosT);
    cudaGetSymbolAddress((void**)&sinT, g_sinT);

    static bool attr_set = false;
    if (!attr_set) {
        cudaFuncSetAttribute(gemm_f16_kernel<true>,
                             cudaFuncAttributeMaxDynamicSharedMemorySize, GEMM_SMEM);
        cudaFuncSetAttribute(gemm_f16_kernel<false>,
                             cudaFuncAttributeMaxDynamicSharedMemorySize, GEMM_SMEM);
        cudaFuncSetAttribute(flash_mma_kernel,
                             cudaFuncAttributeMaxDynamicSharedMemorySize, FL_SMEM);
        attr_set = true;
    }

    // fused input conversions + RoPE tables (1 launch)
    conv_all_kernel<<<(N_PREP + 255) / 256, 256>>>(x, w_attn, w_proj,
                                                   x16, wa, wp, cosT, sinT);

    // 1) qkv = x @ w_attn^T   (fp16 HMMA, fp16 output)
    {
        dim3 grid(QKV_COLS / 128, M_ROWS / 128);
        gemm_f16_kernel<true><<<grid, 256, GEMM_SMEM>>>(x16, wa, qkv16,
                                                        QKV_COLS, C_DIM);
    }
    // 2) RoPE (table-based) q,k only -> head-major
    {
        int total = B_DIM * T_SEQ * H_DIM * 32;
        rope_split_kernel<<<total / 256, 256>>>(qkv16, cosT, sinT, Qh, Kh);
    }
    // 3) flash attention (V read from qkv16) -> yh fp16
    {
        dim3 grid(T_SEQ / 128, B_DIM * H_DIM);
        flash_mma_kernel<<<grid, 256, FL_SMEM>>>(Qh, Kh, qkv16, yh);
    }
    // 4) out = y @ w_proj^T   (fp16 HMMA, fp32 output)
    {
        dim3 grid(C_DIM / 128, M_ROWS / 128);
        gemm_f16_kernel<false><<<grid, 256, GEMM_SMEM>>>(yh, wp, out,
                                                         C_DIM, C_DIM);
    }
}